// round 11
// baseline (speedup 1.0000x reference)
#include <cuda_runtime.h>
#include <cuda_fp16.h>
#include <cstdint>

// Problem constants
#define N_TOK   4096
#define C_BOOKS 128
#define K_CENT  16
#define V_LEN   16
#define IN_DIM  2048
#define OUT_DIM 4096
#define KTOT    2048                   // 128 books * 16 centroids (one-hot K)

// Scratch (allocation-free rule: device globals)
__device__ __half g_A [(size_t)N_TOK  * KTOT];              // dense one-hot A, 16 MB
__device__ __half g_Bt[(size_t)OUT_DIM * KTOT];             // [o][k] k-contiguous, 16 MB

// ---------------------------------------------------------------------------
__device__ __forceinline__ uint32_t smem_u32(const void* p) {
    uint32_t a;
    asm("{ .reg .u64 t; cvta.to.shared.u64 t, %1; cvt.u32.u64 %0, t; }" : "=r"(a) : "l"(p));
    return a;
}

// ---------------------------------------------------------------------------
// Fused prologue: blocks [0, 512) = quant (Chebyshev argmin, exact) writing
// one-hot fp16 rows of A; blocks [512, 2560) = build fp16 LUT matrix B.
// ---------------------------------------------------------------------------
__global__ void __launch_bounds__(256) prologue_kernel(
    const float* __restrict__ x, const float* __restrict__ wgt,
    const float* __restrict__ cents)
{
    __shared__ float sc[32 * 256];
    int tid = threadIdx.x;

    if (blockIdx.x < 512) {
        int blk  = blockIdx.x;
        int lane = tid & 31, w = tid >> 5;
        int token = (blk & 127) * 32 + lane;
        int cbase = (blk >> 7) * 32;

        for (int i = tid; i < 32 * 256; i += 256)
            sc[i] = cents[(size_t)cbase * 256 + i];
        __syncthreads();

        const float* xrow = x + (size_t)token * IN_DIM;
        for (int cl = w * 4; cl < w * 4 + 4; ++cl) {
            int c = cbase + cl;
            float xv[16];
            const float4* xp = (const float4*)(xrow + c * V_LEN);
#pragma unroll
            for (int q = 0; q < 4; ++q) {
                float4 t = xp[q];
                xv[q*4+0] = t.x; xv[q*4+1] = t.y; xv[q*4+2] = t.z; xv[q*4+3] = t.w;
            }
            const float4* cb = (const float4*)(sc + cl * 256);
            float best = 3.4028235e38f; int bi = 0;
#pragma unroll
            for (int k = 0; k < K_CENT; ++k) {
                float d = 0.0f;
#pragma unroll
                for (int q = 0; q < 4; ++q) {
                    float4 t = cb[k * 4 + q];
                    d = fmaxf(d, fabsf(xv[q*4+0] - t.x));
                    d = fmaxf(d, fabsf(xv[q*4+1] - t.y));
                    d = fmaxf(d, fabsf(xv[q*4+2] - t.z));
                    d = fmaxf(d, fabsf(xv[q*4+3] - t.w));
                }
                if (d < best) { best = d; bi = k; }   // strict < == first min (argmin)
            }
            // Write one-hot fp16 row (16 halfs = 32B), no memset needed
            uint32_t val = (bi & 1) ? 0x3C000000u : 0x3C00u;
            uint32_t ww  = (uint32_t)(bi >> 1);
            uint4 q0, q1;
            q0.x = (ww == 0) ? val : 0u; q0.y = (ww == 1) ? val : 0u;
            q0.z = (ww == 2) ? val : 0u; q0.w = (ww == 3) ? val : 0u;
            q1.x = (ww == 4) ? val : 0u; q1.y = (ww == 5) ? val : 0u;
            q1.z = (ww == 6) ? val : 0u; q1.w = (ww == 7) ? val : 0u;
            uint4* dst = (uint4*)(g_A + (size_t)token * KTOT + c * 16);
            dst[0] = q0;
            dst[1] = q1;
        }
    } else {
        int blk = blockIdx.x - 512;               // 0..2047
        int c   = blk & 127;
        int o   = (blk >> 7) * 256 + tid;
        sc[tid] = cents[(size_t)c * 256 + tid];
        __syncthreads();

        float acc[K_CENT];
#pragma unroll
        for (int k = 0; k < K_CENT; ++k) acc[k] = 0.0f;
#pragma unroll
        for (int v = 0; v < V_LEN; ++v) {
            float wv = wgt[(size_t)(c * V_LEN + v) * OUT_DIM + o];
#pragma unroll
            for (int k = 0; k < K_CENT; ++k)
                acc[k] = fmaf(sc[k * V_LEN + v], wv, acc[k]);
        }
        __half2 h[8];
#pragma unroll
        for (int j = 0; j < 8; ++j)
            h[j] = __floats2half2_rn(acc[2 * j], acc[2 * j + 1]);
        uint4* dst = (uint4*)(g_Bt + (size_t)o * KTOT + c * 16);
        dst[0] = *(uint4*)&h[0];
        dst[1] = *(uint4*)&h[4];
    }
}

// ---------------------------------------------------------------------------
// Dense one-hot GEMM: both A and B staged via cp.async (144B pitch),
// A frags via ldmatrix.x4, B frags via ldmatrix.x2 (proven path).
// CTA 128 tok x 128 out, 256 thr, 2-stage double buffer, 2 CTAs/SM.
// ---------------------------------------------------------------------------
#define BSTG    (128 * 144)             // 18432 B per stage
#define SM_A    0                       // 2 stages
#define SM_B    (2 * BSTG)              // 36864, 2 stages
#define SM_BIAS (4 * BSTG)              // 73728
#define SM_TOT  (SM_BIAS + 512)         // 74240

#define MMA(d, a0, a1, a2, a3, b0, b1) \
    asm volatile("mma.sync.aligned.m16n8k16.row.col.f32.f16.f16.f32 " \
        "{%0,%1,%2,%3}, {%4,%5,%6,%7}, {%8,%9}, {%0,%1,%2,%3};" \
        : "+f"((d)[0]), "+f"((d)[1]), "+f"((d)[2]), "+f"((d)[3]) \
        : "r"(a0), "r"(a1), "r"(a2), "r"(a3), "r"(b0), "r"(b1))

__global__ void __launch_bounds__(256, 1) onehot_hmma_kernel(
    const float* __restrict__ bias, float* __restrict__ out)
{
    extern __shared__ __align__(128) unsigned char smem[];
    const uint32_t sb = smem_u32(smem);
    const int tid = threadIdx.x, lane = tid & 31, w = tid >> 5;
    const int ms = w & 3, ns = w >> 2;          // 4 m-strips x 2 n-strips
    const int m0 = blockIdx.y * 128, o0 = blockIdx.x * 128;

    {
        float* sbias = (float*)(smem + SM_BIAS);
        if (tid < 128) sbias[tid] = bias[o0 + tid];
    }

    const __half* gA = g_A  + (size_t)m0 * KTOT;
    const __half* gB = g_Bt + (size_t)o0 * KTOT;

    // Prologue: stages 0, 1 (A + B)
#pragma unroll
    for (int s = 0; s < 2; ++s) {
        uint32_t dstA = sb + SM_A + s * BSTG;
        uint32_t dstB = sb + SM_B + s * BSTG;
        const __half* srcA = gA + s * 64;
        const __half* srcB = gB + s * 64;
#pragma unroll
        for (int r = 0; r < 4; ++r) {
            int i = tid + r * 256, n = i >> 3, ch = i & 7;
            asm volatile("cp.async.cg.shared.global [%0], [%1], 16;"
                :: "r"(dstA + n * 144 + ch * 16), "l"(srcA + (size_t)n * KTOT + ch * 8));
            asm volatile("cp.async.cg.shared.global [%0], [%1], 16;"
                :: "r"(dstB + n * 144 + ch * 16), "l"(srcB + (size_t)n * KTOT + ch * 8));
        }
        asm volatile("cp.async.commit_group;" ::: "memory");
    }

    float acc[2][8][4];
#pragma unroll
    for (int mf = 0; mf < 2; ++mf)
#pragma unroll
        for (int nf = 0; nf < 8; ++nf)
#pragma unroll
            for (int q = 0; q < 4; ++q) acc[mf][nf][q] = 0.0f;

    // ldmatrix.x4 lane address pattern (shared by A and B tiles):
    // lanes 0-7: rows 0-7 / k0-half; 8-15: rows 8-15 / k0; 16-23: rows 0-7 / k8; 24-31: rows 8-15 / k8
    const uint32_t lmx4 = (uint32_t)((lane & 15) * 144 + (lane >> 4) * 16);
    const uint32_t lmb  = (uint32_t)((lane & 7) * 144 + (lane >> 3) * 16);

    for (int s = 0; s < 32; ++s) {
        asm volatile("cp.async.wait_group 1;" ::: "memory");
        __syncthreads();
        uint32_t bufA = sb + SM_A + (s & 1) * BSTG;
        uint32_t bufB = sb + SM_B + (s & 1) * BSTG;
#pragma unroll
        for (int cb = 0; cb < 4; ++cb) {
            // A fragments: two m16k16 frags (rows ms*32 + mf*16 .. +16)
            uint32_t a00, a01, a02, a03, a10, a11, a12, a13;
            {
                uint32_t ka = bufA + (uint32_t)((ms * 32) * 144 + cb * 32) + lmx4;
                asm volatile("ldmatrix.sync.aligned.m8n8.x4.shared.b16 {%0,%1,%2,%3}, [%4];"
                             : "=r"(a00), "=r"(a01), "=r"(a02), "=r"(a03)
                             : "r"(ka));
                asm volatile("ldmatrix.sync.aligned.m8n8.x4.shared.b16 {%0,%1,%2,%3}, [%4];"
                             : "=r"(a10), "=r"(a11), "=r"(a12), "=r"(a13)
                             : "r"(ka + 16u * 144u));
            }
            uint32_t kb = bufB + (uint32_t)(cb * 32) + (uint32_t)(ns * 64 * 144) + lmb;
#pragma unroll
            for (int nf = 0; nf < 8; ++nf) {
                uint32_t b0, b1;
                asm volatile("ldmatrix.sync.aligned.m8n8.x2.shared.b16 {%0,%1}, [%2];"
                             : "=r"(b0), "=r"(b1) : "r"(kb + (uint32_t)(nf * 8 * 144)));
                MMA(acc[0][nf], a00, a01, a02, a03, b0, b1);
                MMA(acc[1][nf], a10, a11, a12, a13, b0, b1);
            }
        }
        __syncthreads();
        if (s + 2 < 32) {
            uint32_t dstA = sb + SM_A + (s & 1) * BSTG;
            uint32_t dstB = sb + SM_B + (s & 1) * BSTG;
            const __half* srcA = gA + (s + 2) * 64;
            const __half* srcB = gB + (s + 2) * 64;
#pragma unroll
            for (int r = 0; r < 4; ++r) {
                int i = tid + r * 256, n = i >> 3, ch = i & 7;
                asm volatile("cp.async.cg.shared.global [%0], [%1], 16;"
                    :: "r"(dstA + n * 144 + ch * 16), "l"(srcA + (size_t)n * KTOT + ch * 8));
                asm volatile("cp.async.cg.shared.global [%0], [%1], 16;"
                    :: "r"(dstB + n * 144 + ch * 16), "l"(srcB + (size_t)n * KTOT + ch * 8));
            }
        }
        asm volatile("cp.async.commit_group;" ::: "memory");
    }

    // Epilogue: add bias, store
    const float* sbias = (const float*)(smem + SM_BIAS);
    const uint32_t c0 = (uint32_t)((lane & 3) * 2);
#pragma unroll
    for (int mf = 0; mf < 2; ++mf) {
        int row = m0 + ms * 32 + mf * 16 + (lane >> 2);
#pragma unroll
        for (int nf = 0; nf < 8; ++nf) {
            int colL = ns * 64 + nf * 8 + (int)c0;
            float2 bv = *(const float2*)(sbias + colL);
            float2 v0 = make_float2(acc[mf][nf][0] + bv.x, acc[mf][nf][1] + bv.y);
            float2 v1 = make_float2(acc[mf][nf][2] + bv.x, acc[mf][nf][3] + bv.y);
            *(float2*)(out + (size_t)row * OUT_DIM + o0 + colL) = v0;
            *(float2*)(out + (size_t)(row + 8) * OUT_DIM + o0 + colL) = v1;
        }
    }
}

// ---------------------------------------------------------------------------
extern "C" void kernel_launch(void* const* d_in, const int* in_sizes, int n_in,
                              void* d_out, int out_size)
{
    const float* x     = (const float*)d_in[0];
    const float* wgt   = (const float*)d_in[1];
    const float* cents = (const float*)d_in[2];
    const float* bias  = (const float*)d_in[3];
    float*       out   = (float*)d_out;

    cudaFuncSetAttribute(onehot_hmma_kernel,
                         cudaFuncAttributeMaxDynamicSharedMemorySize, SM_TOT);

    prologue_kernel<<<2560, 256>>>(x, wgt, cents);
    onehot_hmma_kernel<<<dim3(OUT_DIM / 128, N_TOK / 128), 256, SM_TOT>>>(bias, out);
}

// round 12
// speedup vs baseline: 1.0469x; 1.0469x over previous
#include <cuda_runtime.h>
#include <cuda_fp16.h>
#include <cstdint>

// Problem constants
#define N_TOK   4096
#define C_BOOKS 128
#define K_CENT  16
#define V_LEN   16
#define IN_DIM  2048
#define OUT_DIM 4096
#define KTOT    2048                   // 128 books * 16 centroids (one-hot K)

// Scratch (allocation-free rule: device globals)
__device__ __half g_A [(size_t)N_TOK  * KTOT];              // dense one-hot A, 16 MB
__device__ __half g_Bt[(size_t)OUT_DIM * KTOT];             // [o][k] k-contiguous, 16 MB

// ---------------------------------------------------------------------------
__device__ __forceinline__ uint32_t smem_u32(const void* p) {
    uint32_t a;
    asm("{ .reg .u64 t; cvta.to.shared.u64 t, %1; cvt.u32.u64 %0, t; }" : "=r"(a) : "l"(p));
    return a;
}

// ---------------------------------------------------------------------------
// Fused prologue: blocks [0, 512) = quant (Chebyshev argmin, exact) writing
// one-hot fp16 rows of A; blocks [512, 2560) = build fp16 LUT matrix B.
// ---------------------------------------------------------------------------
__global__ void __launch_bounds__(256) prologue_kernel(
    const float* __restrict__ x, const float* __restrict__ wgt,
    const float* __restrict__ cents)
{
    __shared__ float sc[32 * 256];
    int tid = threadIdx.x;

    if (blockIdx.x < 512) {
        int blk  = blockIdx.x;
        int lane = tid & 31, w = tid >> 5;
        int token = (blk & 127) * 32 + lane;
        int cbase = (blk >> 7) * 32;

        for (int i = tid; i < 32 * 256; i += 256)
            sc[i] = cents[(size_t)cbase * 256 + i];
        __syncthreads();

        const float* xrow = x + (size_t)token * IN_DIM;
        for (int cl = w * 4; cl < w * 4 + 4; ++cl) {
            int c = cbase + cl;
            float xv[16];
            const float4* xp = (const float4*)(xrow + c * V_LEN);
#pragma unroll
            for (int q = 0; q < 4; ++q) {
                float4 t = xp[q];
                xv[q*4+0] = t.x; xv[q*4+1] = t.y; xv[q*4+2] = t.z; xv[q*4+3] = t.w;
            }
            const float4* cb = (const float4*)(sc + cl * 256);
            float best = 3.4028235e38f; int bi = 0;
#pragma unroll
            for (int k = 0; k < K_CENT; ++k) {
                float d = 0.0f;
#pragma unroll
                for (int q = 0; q < 4; ++q) {
                    float4 t = cb[k * 4 + q];
                    d = fmaxf(d, fabsf(xv[q*4+0] - t.x));
                    d = fmaxf(d, fabsf(xv[q*4+1] - t.y));
                    d = fmaxf(d, fabsf(xv[q*4+2] - t.z));
                    d = fmaxf(d, fabsf(xv[q*4+3] - t.w));
                }
                if (d < best) { best = d; bi = k; }   // strict < == first min (argmin)
            }
            // Write one-hot fp16 row (16 halfs = 32B), no memset needed
            uint32_t val = (bi & 1) ? 0x3C000000u : 0x3C00u;
            uint32_t ww  = (uint32_t)(bi >> 1);
            uint4 q0, q1;
            q0.x = (ww == 0) ? val : 0u; q0.y = (ww == 1) ? val : 0u;
            q0.z = (ww == 2) ? val : 0u; q0.w = (ww == 3) ? val : 0u;
            q1.x = (ww == 4) ? val : 0u; q1.y = (ww == 5) ? val : 0u;
            q1.z = (ww == 6) ? val : 0u; q1.w = (ww == 7) ? val : 0u;
            uint4* dst = (uint4*)(g_A + (size_t)token * KTOT + c * 16);
            dst[0] = q0;
            dst[1] = q1;
        }
    } else {
        int blk = blockIdx.x - 512;               // 0..2047
        int c   = blk & 127;
        int o   = (blk >> 7) * 256 + tid;
        sc[tid] = cents[(size_t)c * 256 + tid];
        __syncthreads();

        float acc[K_CENT];
#pragma unroll
        for (int k = 0; k < K_CENT; ++k) acc[k] = 0.0f;
#pragma unroll
        for (int v = 0; v < V_LEN; ++v) {
            float wv = wgt[(size_t)(c * V_LEN + v) * OUT_DIM + o];
#pragma unroll
            for (int k = 0; k < K_CENT; ++k)
                acc[k] = fmaf(sc[k * V_LEN + v], wv, acc[k]);
        }
        __half2 h[8];
#pragma unroll
        for (int j = 0; j < 8; ++j)
            h[j] = __floats2half2_rn(acc[2 * j], acc[2 * j + 1]);
        uint4* dst = (uint4*)(g_Bt + (size_t)o * KTOT + c * 16);
        dst[0] = *(uint4*)&h[0];
        dst[1] = *(uint4*)&h[4];
    }
}

// ---------------------------------------------------------------------------
// Dense one-hot GEMM: both A and B staged via cp.async (144B pitch),
// A frags via ldmatrix.x4, B frags via ldmatrix.x2.
// CTA 128 tok x 128 out, 256 thr, 2-stage double buffer.
// __launch_bounds__(256, 2) pins 2 CTAs/SM (caps regs at 128) — the single
// change vs R11, recovering the occupancy that regs=176 destroyed.
// ---------------------------------------------------------------------------
#define BSTG    (128 * 144)             // 18432 B per stage
#define SM_A    0                       // 2 stages
#define SM_B    (2 * BSTG)              // 36864, 2 stages
#define SM_BIAS (4 * BSTG)              // 73728
#define SM_TOT  (SM_BIAS + 512)         // 74240

#define MMA(d, a0, a1, a2, a3, b0, b1) \
    asm volatile("mma.sync.aligned.m16n8k16.row.col.f32.f16.f16.f32 " \
        "{%0,%1,%2,%3}, {%4,%5,%6,%7}, {%8,%9}, {%0,%1,%2,%3};" \
        : "+f"((d)[0]), "+f"((d)[1]), "+f"((d)[2]), "+f"((d)[3]) \
        : "r"(a0), "r"(a1), "r"(a2), "r"(a3), "r"(b0), "r"(b1))

__global__ void __launch_bounds__(256, 2) onehot_hmma_kernel(
    const float* __restrict__ bias, float* __restrict__ out)
{
    extern __shared__ __align__(128) unsigned char smem[];
    const uint32_t sb = smem_u32(smem);
    const int tid = threadIdx.x, lane = tid & 31, w = tid >> 5;
    const int ms = w & 3, ns = w >> 2;          // 4 m-strips x 2 n-strips
    const int m0 = blockIdx.y * 128, o0 = blockIdx.x * 128;

    {
        float* sbias = (float*)(smem + SM_BIAS);
        if (tid < 128) sbias[tid] = bias[o0 + tid];
    }

    const __half* gA = g_A  + (size_t)m0 * KTOT;
    const __half* gB = g_Bt + (size_t)o0 * KTOT;

    // Prologue: stages 0, 1 (A + B)
#pragma unroll
    for (int s = 0; s < 2; ++s) {
        uint32_t dstA = sb + SM_A + s * BSTG;
        uint32_t dstB = sb + SM_B + s * BSTG;
        const __half* srcA = gA + s * 64;
        const __half* srcB = gB + s * 64;
#pragma unroll
        for (int r = 0; r < 4; ++r) {
            int i = tid + r * 256, n = i >> 3, ch = i & 7;
            asm volatile("cp.async.cg.shared.global [%0], [%1], 16;"
                :: "r"(dstA + n * 144 + ch * 16), "l"(srcA + (size_t)n * KTOT + ch * 8));
            asm volatile("cp.async.cg.shared.global [%0], [%1], 16;"
                :: "r"(dstB + n * 144 + ch * 16), "l"(srcB + (size_t)n * KTOT + ch * 8));
        }
        asm volatile("cp.async.commit_group;" ::: "memory");
    }

    float acc[2][8][4];
#pragma unroll
    for (int mf = 0; mf < 2; ++mf)
#pragma unroll
        for (int nf = 0; nf < 8; ++nf)
#pragma unroll
            for (int q = 0; q < 4; ++q) acc[mf][nf][q] = 0.0f;

    // ldmatrix.x4 lane address pattern (shared by A and B tiles)
    const uint32_t lmx4 = (uint32_t)((lane & 15) * 144 + (lane >> 4) * 16);
    const uint32_t lmb  = (uint32_t)((lane & 7) * 144 + (lane >> 3) * 16);

    for (int s = 0; s < 32; ++s) {
        asm volatile("cp.async.wait_group 1;" ::: "memory");
        __syncthreads();
        uint32_t bufA = sb + SM_A + (s & 1) * BSTG;
        uint32_t bufB = sb + SM_B + (s & 1) * BSTG;
#pragma unroll
        for (int cb = 0; cb < 4; ++cb) {
            uint32_t a00, a01, a02, a03, a10, a11, a12, a13;
            {
                uint32_t ka = bufA + (uint32_t)((ms * 32) * 144 + cb * 32) + lmx4;
                asm volatile("ldmatrix.sync.aligned.m8n8.x4.shared.b16 {%0,%1,%2,%3}, [%4];"
                             : "=r"(a00), "=r"(a01), "=r"(a02), "=r"(a03)
                             : "r"(ka));
                asm volatile("ldmatrix.sync.aligned.m8n8.x4.shared.b16 {%0,%1,%2,%3}, [%4];"
                             : "=r"(a10), "=r"(a11), "=r"(a12), "=r"(a13)
                             : "r"(ka + 16u * 144u));
            }
            uint32_t kb = bufB + (uint32_t)(cb * 32) + (uint32_t)(ns * 64 * 144) + lmb;
#pragma unroll
            for (int nf = 0; nf < 8; ++nf) {
                uint32_t b0, b1;
                asm volatile("ldmatrix.sync.aligned.m8n8.x2.shared.b16 {%0,%1}, [%2];"
                             : "=r"(b0), "=r"(b1) : "r"(kb + (uint32_t)(nf * 8 * 144)));
                MMA(acc[0][nf], a00, a01, a02, a03, b0, b1);
                MMA(acc[1][nf], a10, a11, a12, a13, b0, b1);
            }
        }
        __syncthreads();
        if (s + 2 < 32) {
            uint32_t dstA = sb + SM_A + (s & 1) * BSTG;
            uint32_t dstB = sb + SM_B + (s & 1) * BSTG;
            const __half* srcA = gA + (s + 2) * 64;
            const __half* srcB = gB + (s + 2) * 64;
#pragma unroll
            for (int r = 0; r < 4; ++r) {
                int i = tid + r * 256, n = i >> 3, ch = i & 7;
                asm volatile("cp.async.cg.shared.global [%0], [%1], 16;"
                    :: "r"(dstA + n * 144 + ch * 16), "l"(srcA + (size_t)n * KTOT + ch * 8));
                asm volatile("cp.async.cg.shared.global [%0], [%1], 16;"
                    :: "r"(dstB + n * 144 + ch * 16), "l"(srcB + (size_t)n * KTOT + ch * 8));
            }
        }
        asm volatile("cp.async.commit_group;" ::: "memory");
    }

    // Epilogue: add bias, store
    const float* sbias = (const float*)(smem + SM_BIAS);
    const uint32_t c0 = (uint32_t)((lane & 3) * 2);
#pragma unroll
    for (int mf = 0; mf < 2; ++mf) {
        int row = m0 + ms * 32 + mf * 16 + (lane >> 2);
#pragma unroll
        for (int nf = 0; nf < 8; ++nf) {
            int colL = ns * 64 + nf * 8 + (int)c0;
            float2 bv = *(const float2*)(sbias + colL);
            float2 v0 = make_float2(acc[mf][nf][0] + bv.x, acc[mf][nf][1] + bv.y);
            float2 v1 = make_float2(acc[mf][nf][2] + bv.x, acc[mf][nf][3] + bv.y);
            *(float2*)(out + (size_t)row * OUT_DIM + o0 + colL) = v0;
            *(float2*)(out + (size_t)(row + 8) * OUT_DIM + o0 + colL) = v1;
        }
    }
}

// ---------------------------------------------------------------------------
extern "C" void kernel_launch(void* const* d_in, const int* in_sizes, int n_in,
                              void* d_out, int out_size)
{
    const float* x     = (const float*)d_in[0];
    const float* wgt   = (const float*)d_in[1];
    const float* cents = (const float*)d_in[2];
    const float* bias  = (const float*)d_in[3];
    float*       out   = (float*)d_out;

    cudaFuncSetAttribute(onehot_hmma_kernel,
                         cudaFuncAttributeMaxDynamicSharedMemorySize, SM_TOT);

    prologue_kernel<<<2560, 256>>>(x, wgt, cents);
    onehot_hmma_kernel<<<dim3(OUT_DIM / 128, N_TOK / 128), 256, SM_TOT>>>(bias, out);
}

// round 13
// speedup vs baseline: 1.0591x; 1.0117x over previous
#include <cuda_runtime.h>
#include <cuda_fp16.h>
#include <cstdint>

// Problem constants
#define N_TOK   4096
#define C_BOOKS 128
#define K_CENT  16
#define V_LEN   16
#define IN_DIM  2048
#define OUT_DIM 4096
#define KTOT    2048                   // 128 books * 16 centroids (one-hot K)

// Scratch (allocation-free rule: device globals)
__device__ unsigned char g_idxT[(size_t)C_BOOKS * N_TOK];   // [c][token]
__device__ __half g_Bt[(size_t)OUT_DIM * KTOT];             // [o][k] k-contiguous, 16 MB

// ---------------------------------------------------------------------------
__device__ __forceinline__ uint32_t smem_u32(const void* p) {
    uint32_t a;
    asm("{ .reg .u64 t; cvta.to.shared.u64 t, %1; cvt.u32.u64 %0, t; }" : "=r"(a) : "l"(p));
    return a;
}
// one-hot half2: t==0 -> (1,0), t==1 -> (0,1), else (0,0)
__device__ __forceinline__ uint32_t oh(uint32_t t) {
    return t == 0u ? 0x3C00u : (t == 1u ? 0x3C000000u : 0u);
}

// ---------------------------------------------------------------------------
// Fused prologue: blocks [0, 512) = quant (Chebyshev argmin, exact) -> g_idxT;
// blocks [512, 2560) = build fp16 LUT matrix B. (R9 version, 31us known.)
// ---------------------------------------------------------------------------
__global__ void __launch_bounds__(256) prologue_kernel(
    const float* __restrict__ x, const float* __restrict__ wgt,
    const float* __restrict__ cents)
{
    __shared__ float sc[32 * 256];
    int tid = threadIdx.x;

    if (blockIdx.x < 512) {
        int blk  = blockIdx.x;
        int lane = tid & 31, w = tid >> 5;
        int token = (blk & 127) * 32 + lane;
        int cbase = (blk >> 7) * 32;

        for (int i = tid; i < 32 * 256; i += 256)
            sc[i] = cents[(size_t)cbase * 256 + i];
        __syncthreads();

        const float* xrow = x + (size_t)token * IN_DIM;
        for (int cl = w * 4; cl < w * 4 + 4; ++cl) {
            int c = cbase + cl;
            float xv[16];
            const float4* xp = (const float4*)(xrow + c * V_LEN);
#pragma unroll
            for (int q = 0; q < 4; ++q) {
                float4 t = xp[q];
                xv[q*4+0] = t.x; xv[q*4+1] = t.y; xv[q*4+2] = t.z; xv[q*4+3] = t.w;
            }
            const float4* cb = (const float4*)(sc + cl * 256);
            float best = 3.4028235e38f; int bi = 0;
#pragma unroll
            for (int k = 0; k < K_CENT; ++k) {
                float d = 0.0f;
#pragma unroll
                for (int q = 0; q < 4; ++q) {
                    float4 t = cb[k * 4 + q];
                    d = fmaxf(d, fabsf(xv[q*4+0] - t.x));
                    d = fmaxf(d, fabsf(xv[q*4+1] - t.y));
                    d = fmaxf(d, fabsf(xv[q*4+2] - t.z));
                    d = fmaxf(d, fabsf(xv[q*4+3] - t.w));
                }
                if (d < best) { best = d; bi = k; }   // strict < == first min (argmin)
            }
            g_idxT[(size_t)c * N_TOK + token] = (unsigned char)bi;
        }
    } else {
        int blk = blockIdx.x - 512;               // 0..2047
        int c   = blk & 127;
        int o   = (blk >> 7) * 256 + tid;
        sc[tid] = cents[(size_t)c * 256 + tid];
        __syncthreads();

        float acc[K_CENT];
#pragma unroll
        for (int k = 0; k < K_CENT; ++k) acc[k] = 0.0f;
#pragma unroll
        for (int v = 0; v < V_LEN; ++v) {
            float wv = wgt[(size_t)(c * V_LEN + v) * OUT_DIM + o];
#pragma unroll
            for (int k = 0; k < K_CENT; ++k)
                acc[k] = fmaf(sc[k * V_LEN + v], wv, acc[k]);
        }
        __half2 h[8];
#pragma unroll
        for (int j = 0; j < 8; ++j)
            h[j] = __floats2half2_rn(acc[2 * j], acc[2 * j + 1]);
        uint4* dst = (uint4*)(g_Bt + (size_t)o * KTOT + c * 16);
        dst[0] = *(uint4*)&h[0];
        dst[1] = *(uint4*)&h[4];
    }
}

// ---------------------------------------------------------------------------
// Dense one-hot GEMM (R10 structure, K-chunk 128 -> 16 iterations).
// CTA 128 tok x 128 out, 256 thr (8 warps, warp tile 32x64), 2 CTAs/SM.
// A synthesized in registers from idx bytes (no A smem traffic).
// B staged 128 rows x 256B payload at 272B pitch (conflict-free ldmatrix).
// ---------------------------------------------------------------------------
#define SM_IDX  0                       // 128 books x 128 tokens = 16 KB
#define BPITCH  272
#define BSTG    (128 * BPITCH)          // 34816 B per stage
#define SM_B    16384
#define SM_BIAS (SM_B + 2 * BSTG)       // 86016
#define SM_TOT  (SM_BIAS + 512)         // 86528

#define MMA(d, a0, a1, a2, a3, b0, b1) \
    asm volatile("mma.sync.aligned.m16n8k16.row.col.f32.f16.f16.f32 " \
        "{%0,%1,%2,%3}, {%4,%5,%6,%7}, {%8,%9}, {%0,%1,%2,%3};" \
        : "+f"((d)[0]), "+f"((d)[1]), "+f"((d)[2]), "+f"((d)[3]) \
        : "r"(a0), "r"(a1), "r"(a2), "r"(a3), "r"(b0), "r"(b1))

__global__ void __launch_bounds__(256, 2) onehot_hmma_kernel(
    const float* __restrict__ bias, float* __restrict__ out)
{
    extern __shared__ __align__(128) unsigned char smem[];
    const uint32_t sb = smem_u32(smem);
    const int tid = threadIdx.x, lane = tid & 31, w = tid >> 5;
    const int ms = w & 3, ns = w >> 2;          // 4 m-strips x 2 n-strips
    const int m0 = blockIdx.y * 128, o0 = blockIdx.x * 128;

    // Stage idx (128 books x 128 tokens) + bias
    {
        uint4* si = (uint4*)(smem + SM_IDX);
        for (int i = tid; i < 1024; i += 256)
            si[i] = *(const uint4*)(g_idxT + ((size_t)(i >> 3) << 12) + m0 + (i & 7) * 16);
        float* sbias = (float*)(smem + SM_BIAS);
        if (tid < 128) sbias[tid] = bias[o0 + tid];
    }

    const __half* gB = g_Bt + (size_t)o0 * KTOT;

    // Prologue: stages 0, 1 (each = 128 n-rows x 128 k halfs)
#pragma unroll
    for (int s = 0; s < 2; ++s) {
        uint32_t dst = sb + SM_B + s * BSTG;
        const __half* src = gB + s * 128;
#pragma unroll
        for (int r = 0; r < 8; ++r) {
            int i = tid + r * 256, n = i >> 4, ch = i & 15;
            asm volatile("cp.async.cg.shared.global [%0], [%1], 16;"
                :: "r"(dst + n * BPITCH + ch * 16), "l"(src + (size_t)n * KTOT + ch * 8));
        }
        asm volatile("cp.async.commit_group;" ::: "memory");
    }

    float acc[2][8][4];
#pragma unroll
    for (int mf = 0; mf < 2; ++mf)
#pragma unroll
        for (int nf = 0; nf < 8; ++nf)
#pragma unroll
            for (int q = 0; q < 4; ++q) acc[mf][nf][q] = 0.0f;

    const uint32_t c0  = (uint32_t)((lane & 3) * 2);
    const uint32_t lmb = (uint32_t)((lane & 7) * BPITCH + (lane >> 3) * 16);
    const unsigned char* s_idx = smem + SM_IDX;
    const int rbase = ms * 32 + (lane >> 2);

    for (int s = 0; s < 16; ++s) {
        asm volatile("cp.async.wait_group 1;" ::: "memory");
        __syncthreads();
        uint32_t bufB = sb + SM_B + (s & 1) * BSTG;
#pragma unroll
        for (int cb = 0; cb < 8; ++cb) {
            int c = s * 8 + cb;
            const unsigned char* ip = s_idx + (c << 7) + rbase;
            uint32_t i0 = ip[0], i1 = ip[8], i2 = ip[16], i3 = ip[24];
            uint32_t t0 = i0 ^ c0, t1 = i1 ^ c0, t2 = i2 ^ c0, t3 = i3 ^ c0;
            uint32_t a00 = oh(t0),     a01 = oh(t1);
            uint32_t a02 = oh(t0 ^ 8), a03 = oh(t1 ^ 8);
            uint32_t a10 = oh(t2),     a11 = oh(t3);
            uint32_t a12 = oh(t2 ^ 8), a13 = oh(t3 ^ 8);
            uint32_t kb = bufB + (uint32_t)(cb * 32) + (uint32_t)(ns * 64 * BPITCH) + lmb;
#pragma unroll
            for (int nf = 0; nf < 8; ++nf) {
                uint32_t b0, b1;
                asm volatile("ldmatrix.sync.aligned.m8n8.x2.shared.b16 {%0,%1}, [%2];"
                             : "=r"(b0), "=r"(b1) : "r"(kb + (uint32_t)(nf * 8 * BPITCH)));
                MMA(acc[0][nf], a00, a01, a02, a03, b0, b1);
                MMA(acc[1][nf], a10, a11, a12, a13, b0, b1);
            }
        }
        __syncthreads();
        if (s + 2 < 16) {
            uint32_t dst = sb + SM_B + (s & 1) * BSTG;
            const __half* src = gB + (s + 2) * 128;
#pragma unroll
            for (int r = 0; r < 8; ++r) {
                int i = tid + r * 256, n = i >> 4, ch = i & 15;
                asm volatile("cp.async.cg.shared.global [%0], [%1], 16;"
                    :: "r"(dst + n * BPITCH + ch * 16), "l"(src + (size_t)n * KTOT + ch * 8));
            }
        }
        asm volatile("cp.async.commit_group;" ::: "memory");
    }

    // Epilogue: add bias, store
    const float* sbias = (const float*)(smem + SM_BIAS);
#pragma unroll
    for (int mf = 0; mf < 2; ++mf) {
        int row = m0 + ms * 32 + mf * 16 + (lane >> 2);
#pragma unroll
        for (int nf = 0; nf < 8; ++nf) {
            int colL = ns * 64 + nf * 8 + (int)c0;
            float2 bv = *(const float2*)(sbias + colL);
            float2 v0 = make_float2(acc[mf][nf][0] + bv.x, acc[mf][nf][1] + bv.y);
            float2 v1 = make_float2(acc[mf][nf][2] + bv.x, acc[mf][nf][3] + bv.y);
            *(float2*)(out + (size_t)row * OUT_DIM + o0 + colL) = v0;
            *(float2*)(out + (size_t)(row + 8) * OUT_DIM + o0 + colL) = v1;
        }
    }
}

// ---------------------------------------------------------------------------
extern "C" void kernel_launch(void* const* d_in, const int* in_sizes, int n_in,
                              void* d_out, int out_size)
{
    const float* x     = (const float*)d_in[0];
    const float* wgt   = (const float*)d_in[1];
    const float* cents = (const float*)d_in[2];
    const float* bias  = (const float*)d_in[3];
    float*       out   = (float*)d_out;

    cudaFuncSetAttribute(onehot_hmma_kernel,
                         cudaFuncAttributeMaxDynamicSharedMemorySize, SM_TOT);

    prologue_kernel<<<2560, 256>>>(x, wgt, cents);
    onehot_hmma_kernel<<<dim3(OUT_DIM / 128, N_TOK / 128), 256, SM_TOT>>>(bias, out);
}

// round 15
// speedup vs baseline: 1.1580x; 1.0934x over previous
#include <cuda_runtime.h>
#include <cuda_fp16.h>
#include <cstdint>

// Problem constants
#define N_TOK   4096
#define C_BOOKS 128
#define K_CENT  16
#define V_LEN   16
#define IN_DIM  2048
#define OUT_DIM 4096
#define KTOT    2048                   // 128 books * 16 centroids (one-hot K)

// Scratch (allocation-free rule: device globals)
__device__ unsigned char g_idxT[(size_t)C_BOOKS * N_TOK];   // [c][token]
__device__ __half g_Bt[(size_t)OUT_DIM * KTOT];             // [o][k] k-contiguous, 16 MB

// ---------------------------------------------------------------------------
__device__ __forceinline__ uint32_t smem_u32(const void* p) {
    uint32_t a;
    asm("{ .reg .u64 t; cvta.to.shared.u64 t, %1; cvt.u32.u64 %0, t; }" : "=r"(a) : "l"(p));
    return a;
}
// one-hot half2: t==0 -> (1,0), t==1 -> (0,1), else (0,0)
__device__ __forceinline__ uint32_t oh(uint32_t t) {
    return t == 0u ? 0x3C00u : (t == 1u ? 0x3C000000u : 0u);
}

// ---------------------------------------------------------------------------
// Fused prologue: blocks [0, 512) = quant (Chebyshev argmin, exact) -> g_idxT;
// blocks [512, 2560) = build fp16 LUT matrix B. (Known 31us.)
// ---------------------------------------------------------------------------
__global__ void __launch_bounds__(256) prologue_kernel(
    const float* __restrict__ x, const float* __restrict__ wgt,
    const float* __restrict__ cents)
{
    __shared__ float sc[32 * 256];
    int tid = threadIdx.x;

    if (blockIdx.x < 512) {
        int blk  = blockIdx.x;
        int lane = tid & 31, w = tid >> 5;
        int token = (blk & 127) * 32 + lane;
        int cbase = (blk >> 7) * 32;

        for (int i = tid; i < 32 * 256; i += 256)
            sc[i] = cents[(size_t)cbase * 256 + i];
        __syncthreads();

        const float* xrow = x + (size_t)token * IN_DIM;
        for (int cl = w * 4; cl < w * 4 + 4; ++cl) {
            int c = cbase + cl;
            float xv[16];
            const float4* xp = (const float4*)(xrow + c * V_LEN);
#pragma unroll
            for (int q = 0; q < 4; ++q) {
                float4 t = xp[q];
                xv[q*4+0] = t.x; xv[q*4+1] = t.y; xv[q*4+2] = t.z; xv[q*4+3] = t.w;
            }
            const float4* cb = (const float4*)(sc + cl * 256);
            float best = 3.4028235e38f; int bi = 0;
#pragma unroll
            for (int k = 0; k < K_CENT; ++k) {
                float d = 0.0f;
#pragma unroll
                for (int q = 0; q < 4; ++q) {
                    float4 t = cb[k * 4 + q];
                    d = fmaxf(d, fabsf(xv[q*4+0] - t.x));
                    d = fmaxf(d, fabsf(xv[q*4+1] - t.y));
                    d = fmaxf(d, fabsf(xv[q*4+2] - t.z));
                    d = fmaxf(d, fabsf(xv[q*4+3] - t.w));
                }
                if (d < best) { best = d; bi = k; }   // strict < == first min (argmin)
            }
            g_idxT[(size_t)c * N_TOK + token] = (unsigned char)bi;
        }
    } else {
        int blk = blockIdx.x - 512;               // 0..2047
        int c   = blk & 127;
        int o   = (blk >> 7) * 256 + tid;
        sc[tid] = cents[(size_t)c * 256 + tid];
        __syncthreads();

        float acc[K_CENT];
#pragma unroll
        for (int k = 0; k < K_CENT; ++k) acc[k] = 0.0f;
#pragma unroll
        for (int v = 0; v < V_LEN; ++v) {
            float wv = wgt[(size_t)(c * V_LEN + v) * OUT_DIM + o];
#pragma unroll
            for (int k = 0; k < K_CENT; ++k)
                acc[k] = fmaf(sc[k * V_LEN + v], wv, acc[k]);
        }
        __half2 h[8];
#pragma unroll
        for (int j = 0; j < 8; ++j)
            h[j] = __floats2half2_rn(acc[2 * j], acc[2 * j + 1]);
        uint4* dst = (uint4*)(g_Bt + (size_t)o * KTOT + c * 16);
        dst[0] = *(uint4*)&h[0];
        dst[1] = *(uint4*)&h[4];
    }
}

// ---------------------------------------------------------------------------
// Dense one-hot GEMM — R10 structure, with GROUP-SCOPED barriers:
// warps 0-3 (ns=0) own B rows 0-63; warps 4-7 (ns=1) own rows 64-127.
// Each 128-thread half cp.asyncs its own rows and syncs via bar.sync (1+ns).
// Single full __syncthreads only for the read-only idx/bias staging.
// ---------------------------------------------------------------------------
#define SM_IDX  0                       // 128 books x 128 tokens = 16 KB
#define BSTG    (128 * 144)             // 18432 B per stage
#define SM_B    16384
#define SM_BIAS (SM_B + 2 * BSTG)       // 53248
#define SM_TOT  (SM_BIAS + 512)         // 53760

#define MMA(d, a0, a1, a2, a3, b0, b1) \
    asm volatile("mma.sync.aligned.m16n8k16.row.col.f32.f16.f16.f32 " \
        "{%0,%1,%2,%3}, {%4,%5,%6,%7}, {%8,%9}, {%0,%1,%2,%3};" \
        : "+f"((d)[0]), "+f"((d)[1]), "+f"((d)[2]), "+f"((d)[3]) \
        : "r"(a0), "r"(a1), "r"(a2), "r"(a3), "r"(b0), "r"(b1))

#define GBAR(id) asm volatile("bar.sync %0, 128;" :: "r"(id) : "memory")

__global__ void __launch_bounds__(256, 1) onehot_hmma_kernel(
    const float* __restrict__ bias, float* __restrict__ out)
{
    extern __shared__ __align__(128) unsigned char smem[];
    const uint32_t sb = smem_u32(smem);
    const int tid = threadIdx.x, lane = tid & 31, w = tid >> 5;
    const int ms = w & 3, ns = w >> 2;          // 4 m-strips x 2 n-strips
    const int gtid = tid & 127;                 // thread id within n-half group
    const int gbar = 1 + ns;                    // named barrier per group
    const int m0 = blockIdx.y * 128, o0 = blockIdx.x * 128;

    const __half* gB = g_Bt + (size_t)o0 * KTOT;

    // Prologue cp.async: each group loads ITS 64 B-rows for stages 0, 1
#pragma unroll
    for (int s = 0; s < 2; ++s) {
        uint32_t dst = sb + SM_B + s * BSTG;
        const __half* src = gB + s * 64;
#pragma unroll
        for (int r = 0; r < 4; ++r) {
            int i = gtid + r * 128, n = ns * 64 + (i >> 3), ch = i & 7;
            asm volatile("cp.async.cg.shared.global [%0], [%1], 16;"
                :: "r"(dst + n * 144 + ch * 16), "l"(src + (size_t)n * KTOT + ch * 8));
        }
        asm volatile("cp.async.commit_group;" ::: "memory");
    }

    // Stage idx (read-only afterward) + bias; single full-block sync
    {
        uint4* si = (uint4*)(smem + SM_IDX);
        for (int i = tid; i < 1024; i += 256)
            si[i] = *(const uint4*)(g_idxT + ((size_t)(i >> 3) << 12) + m0 + (i & 7) * 16);
        float* sbias = (float*)(smem + SM_BIAS);
        if (tid < 128) sbias[tid] = bias[o0 + tid];
    }
    __syncthreads();

    float acc[2][8][4];
#pragma unroll
    for (int mf = 0; mf < 2; ++mf)
#pragma unroll
        for (int nf = 0; nf < 8; ++nf)
#pragma unroll
            for (int q = 0; q < 4; ++q) acc[mf][nf][q] = 0.0f;

    const uint32_t c0  = (uint32_t)((lane & 3) * 2);
    const uint32_t lmb = (uint32_t)((lane & 7) * 144 + (lane >> 3) * 16);
    const unsigned char* s_idx = smem + SM_IDX;
    const int rbase = ms * 32 + (lane >> 2);

    for (int s = 0; s < 32; ++s) {
        asm volatile("cp.async.wait_group 1;" ::: "memory");
        GBAR(gbar);                       // group's half of stage s ready
        uint32_t bufB = sb + SM_B + (s & 1) * BSTG;
#pragma unroll
        for (int cb = 0; cb < 4; ++cb) {
            int c = s * 4 + cb;
            const unsigned char* ip = s_idx + (c << 7) + rbase;
            uint32_t i0 = ip[0], i1 = ip[8], i2 = ip[16], i3 = ip[24];
            uint32_t t0 = i0 ^ c0, t1 = i1 ^ c0, t2 = i2 ^ c0, t3 = i3 ^ c0;
            uint32_t a00 = oh(t0),     a01 = oh(t1);
            uint32_t a02 = oh(t0 ^ 8), a03 = oh(t1 ^ 8);
            uint32_t a10 = oh(t2),     a11 = oh(t3);
            uint32_t a12 = oh(t2 ^ 8), a13 = oh(t3 ^ 8);
            uint32_t kb = bufB + (uint32_t)(cb * 32) + (uint32_t)(ns * 64 * 144) + lmb;
#pragma unroll
            for (int nf = 0; nf < 8; ++nf) {
                uint32_t b0, b1;
                asm volatile("ldmatrix.sync.aligned.m8n8.x2.shared.b16 {%0,%1}, [%2];"
                             : "=r"(b0), "=r"(b1) : "r"(kb + (uint32_t)(nf * 8 * 144)));
                MMA(acc[0][nf], a00, a01, a02, a03, b0, b1);
                MMA(acc[1][nf], a10, a11, a12, a13, b0, b1);
            }
        }
        GBAR(gbar);                       // group done reading buffer (s&1)
        if (s + 2 < 32) {
            uint32_t dst = sb + SM_B + (s & 1) * BSTG;
            const __half* src = gB + (s + 2) * 64;
#pragma unroll
            for (int r = 0; r < 4; ++r) {
                int i = gtid + r * 128, n = ns * 64 + (i >> 3), ch = i & 7;
                asm volatile("cp.async.cg.shared.global [%0], [%1], 16;"
                    :: "r"(dst + n * 144 + ch * 16), "l"(src + (size_t)n * KTOT + ch * 8));
            }
        }
        asm volatile("cp.async.commit_group;" ::: "memory");
    }

    // Epilogue: add bias, store
    const float* sbias = (const float*)(smem + SM_BIAS);
#pragma unroll
    for (int mf = 0; mf < 2; ++mf) {
        int row = m0 + ms * 32 + mf * 16 + (lane >> 2);
#pragma unroll
        for (int nf = 0; nf < 8; ++nf) {
            int colL = ns * 64 + nf * 8 + (int)c0;
            float2 bv = *(const float2*)(sbias + colL);
            float2 v0 = make_float2(acc[mf][nf][0] + bv.x, acc[mf][nf][1] + bv.y);
            float2 v1 = make_float2(acc[mf][nf][2] + bv.x, acc[mf][nf][3] + bv.y);
            *(float2*)(out + (size_t)row * OUT_DIM + o0 + colL) = v0;
            *(float2*)(out + (size_t)(row + 8) * OUT_DIM + o0 + colL) = v1;
        }
    }
}

// ---------------------------------------------------------------------------
extern "C" void kernel_launch(void* const* d_in, const int* in_sizes, int n_in,
                              void* d_out, int out_size)
{
    const float* x     = (const float*)d_in[0];
    const float* wgt   = (const float*)d_in[1];
    const float* cents = (const float*)d_in[2];
    const float* bias  = (const float*)d_in[3];
    float*       out   = (float*)d_out;

    cudaFuncSetAttribute(onehot_hmma_kernel,
                         cudaFuncAttributeMaxDynamicSharedMemorySize, SM_TOT);

    prologue_kernel<<<2560, 256>>>(x, wgt, cents);
    onehot_hmma_kernel<<<dim3(OUT_DIM / 128, N_TOK / 128), 256, SM_TOT>>>(bias, out);
}